// round 8
// baseline (speedup 1.0000x reference)
#include <cuda_runtime.h>

// Fixed shapes.
#define Bv 2
#define Cv 3
#define Dv 128
#define Hv 192
#define Wv 192
#define PW 196             // padded row stride: 196 = 4 (mod 32) -> conflict-free
                           // float4 row sweeps AND scalar column sweeps
#define HW (Hv * Wv)

// ---------------------------------------------------------------------------
// Kernel 1: fused x-solve (W) + y-solve (H). One CTA per (b,c,d) slice.
//  - warp w loads ONLY its own 32 rows -> __syncwarp -> x-sweep (no CTA barrier)
//  - x-sweeps vectorized float4 (4 FFMA chain steps per LDS.128/STS.128)
//  - single __syncthreads before y; y-bwd streams straight to global
// ---------------------------------------------------------------------------
__global__ __launch_bounds__(192, 1)
void xy_solve_kernel(const float* __restrict__ in, float* __restrict__ out,
                     const float* __restrict__ ax, const float* __restrict__ bx,
                     const float* __restrict__ cx,
                     const float* __restrict__ ay, const float* __restrict__ by,
                     const float* __restrict__ cy)
{
    extern __shared__ float sm[];
    float* tile  = sm;                       // Hv * PW  (150528 B, 16B-aligned)
    float* s_cxs = tile + Hv * PW;           // 192: s_cxs[i] = cx[i-1], [0] unused
    float* s_iax = s_cxs + Wv;               // 192: 1/ax
    float* s_fx  = s_iax + Wv;               // 192: bx/ax, [191] unused
    float* s_cys = s_fx + Wv;                // 192: cy shifted
    float* s_iay = s_cys + Hv;               // 192: 1/ay
    float* s_fy  = s_iay + Hv;               // 192: by/ay, [191] unused

    const int t    = threadIdx.x;
    const int warp = t >> 5;
    const int lane = t & 31;

    // ---- x-coefficients: each warp writes the FULL set (identical values ->
    // benign race); lets each warp proceed after __syncwarp only. ------------
    for (int i = lane; i < Wv; i += 32) {
        float a = ax[i];
        s_iax[i] = 1.0f / a;
        s_cxs[i] = (i >= 1)      ? cx[i - 1]   : 0.0f;
        s_fx[i]  = (i < Wv - 1)  ? bx[i] / a   : 0.0f;
    }

    // ---- y-coefficients: single writer (thread t), consumed after the full
    // barrier below. ----------------------------------------------------------
    if (t < Hv) {
        float a = ay[t];
        s_iay[t] = 1.0f / a;
        s_cys[t] = (t >= 1)      ? cy[t - 1]   : 0.0f;
        s_fy[t]  = (t < Hv - 1)  ? by[t] / a   : 0.0f;
    }

    // ---- warp-local fill: warp w loads rows [32w, 32w+32) as float4 --------
    {
        const float4* g4 = (const float4*)(in + (size_t)blockIdx.x * HW);
        const int base = warp * 1536;        // 32 rows * 48 float4
        #pragma unroll
        for (int m = 0; m < 48; m++) {
            const int idx = base + m * 32 + lane;   // global float4 index
            const int row = idx / 48;
            const int c4  = idx % 48;
            float4 v = g4[idx];
            *(float4*)(tile + row * PW + c4 * 4) = v;
        }
    }
    __syncwarp();

    // ---- x-solve: thread t owns row h = t (its warp loaded it) --------------
    {
        float* row = tile + t * PW;
        float carry = row[0];
        // scalar head i = 1..3
        #pragma unroll
        for (int i = 1; i < 4; i++) {
            carry = fmaf(-s_cxs[i], carry, row[i]);
            row[i] = carry;
        }
        // vector body i = 4..191 (47 aligned groups)
        #pragma unroll 4
        for (int g = 4; g < Wv; g += 4) {
            float4 v  = *(const float4*)(row + g);
            float4 cc = *(const float4*)(s_cxs + g);
            v.x = fmaf(-cc.x, carry, v.x);
            v.y = fmaf(-cc.y, v.x, v.y);
            v.z = fmaf(-cc.z, v.y, v.z);
            v.w = fmaf(-cc.w, v.z, v.w);
            carry = v.w;
            *(float4*)(row + g) = v;
        }
        // backward
        carry = carry * s_iax[Wv - 1];
        row[Wv - 1] = carry;
        #pragma unroll
        for (int i = Wv - 2; i >= Wv - 4; i--) {     // scalar head 190..188
            carry = fmaf(-s_fx[i], carry, row[i] * s_iax[i]);
            row[i] = carry;
        }
        #pragma unroll 4
        for (int g = Wv - 8; g >= 0; g -= 4) {       // vector body 187..0
            float4 v  = *(const float4*)(row + g);
            float4 ff = *(const float4*)(s_fx + g);
            float4 ia = *(const float4*)(s_iax + g);
            v.w = fmaf(-ff.w, carry, v.w * ia.w);
            v.z = fmaf(-ff.z, v.w, v.z * ia.z);
            v.y = fmaf(-ff.y, v.z, v.y * ia.y);
            v.x = fmaf(-ff.x, v.y, v.x * ia.x);
            carry = v.x;
            *(float4*)(row + g) = v;
        }
    }
    __syncthreads();   // the only full-CTA barrier in the data path

    // ---- y-solve: thread t owns column w = t; bwd streams to global ---------
    {
        float carry = tile[t];
        #pragma unroll 8
        for (int i = 1; i < Hv; i++) {
            carry = fmaf(-s_cys[i], carry, tile[i * PW + t]);
            tile[i * PW + t] = carry;
        }
        float* o = out + (size_t)blockIdx.x * HW;
        carry = carry * s_iay[Hv - 1];
        o[(Hv - 1) * Wv + t] = carry;
        #pragma unroll 8
        for (int i = Hv - 2; i >= 0; i--) {
            carry = fmaf(-s_fy[i], carry, tile[i * PW + t] * s_iay[i]);
            o[i * Wv + t] = carry;
        }
    }
}

// ---------------------------------------------------------------------------
// Kernel 2: z-solve (D), in-place. Register-resident column per thread.
// (Unchanged from R5: 36.4us, DRAM 58% — protected.)
// ---------------------------------------------------------------------------
__global__ __launch_bounds__(192, 2)
void z_solve_kernel(float* __restrict__ io,
                    const float* __restrict__ az, const float* __restrict__ bz,
                    const float* __restrict__ cz)
{
    __shared__ float s_c[Dv - 1];
    __shared__ float s_ia[Dv];
    __shared__ float s_f[Dv - 1];

    const int t = threadIdx.x;
    if (t < Dv)     { s_ia[t] = 1.0f / az[t]; }
    if (t < Dv - 1) { s_c[t] = cz[t]; s_f[t] = bz[t] / az[t]; }
    __syncthreads();

    const int n  = blockIdx.x;            // over B*C*H
    const int h  = n % Hv;
    const int bc = n / Hv;
    float* g = io + (size_t)bc * (Dv * HW) + (size_t)h * Wv + t;

    float y[Dv];
    #pragma unroll
    for (int d = 0; d < Dv; d++)
        y[d] = g[(size_t)d * HW];

    #pragma unroll
    for (int d = 1; d < Dv; d++)
        y[d] = fmaf(-s_c[d - 1], y[d - 1], y[d]);

    float carry = y[Dv - 1] * s_ia[Dv - 1];
    g[(size_t)(Dv - 1) * HW] = carry;
    #pragma unroll
    for (int d = Dv - 2; d >= 0; d--) {
        carry = fmaf(-s_f[d], carry, y[d] * s_ia[d]);
        g[(size_t)d * HW] = carry;
    }
}

// ---------------------------------------------------------------------------
extern "C" void kernel_launch(void* const* d_in, const int* in_sizes, int n_in,
                              void* d_out, int out_size)
{
    const float* field = (const float*)d_in[0];
    const float* ax = (const float*)d_in[1];
    const float* bx = (const float*)d_in[2];
    const float* cx = (const float*)d_in[3];
    const float* ay = (const float*)d_in[4];
    const float* by = (const float*)d_in[5];
    const float* cy = (const float*)d_in[6];
    const float* az = (const float*)d_in[7];
    const float* bz = (const float*)d_in[8];
    const float* cz = (const float*)d_in[9];
    float* out = (float*)d_out;

    const int smem_xy = (Hv * PW + 6 * 192) * (int)sizeof(float);

    cudaFuncSetAttribute(xy_solve_kernel,
                         cudaFuncAttributeMaxDynamicSharedMemorySize, smem_xy);

    xy_solve_kernel<<<Bv * Cv * Dv, 192, smem_xy>>>(field, out,
                                                    ax, bx, cx, ay, by, cy);
    z_solve_kernel<<<Bv * Cv * Hv, 192>>>(out, az, bz, cz);
}